// round 1
// baseline (speedup 1.0000x reference)
#include <cuda_runtime.h>
#include <math.h>

#define TB      32768      // T*B images
#define T_STEPS 64
#define BATCH   512
#define NB      5120       // LSTM batch = B*10
#define HID     112
#define G4      448        // 4*HID

// ---------------- scratch (device globals; no runtime allocation) ----------------
__device__ float g_f1[(size_t)TB * 1440];              // (TB,10,12,12)
__device__ float g_f2[(size_t)TB * 720];               // (TB,20,6,6)
__device__ float g_x [(size_t)T_STEPS * NB * 36];      // (T,NB,36)
__device__ float g_G [(size_t)T_STEPS * NB * G4];      // (T,NB,448) = xW + biases
__device__ float g_h [2][(size_t)NB * HID];            // double-buffered hidden
__device__ float g_c [(size_t)NB * HID];               // cell state (in-place)

// ---------------- init h,c ----------------
__global__ void k_init(const float* __restrict__ h0, const float* __restrict__ c0) {
    int idx = blockIdx.x * 256 + threadIdx.x;
    if (idx < NB * HID) {
        int k = idx % HID;
        g_h[0][idx] = h0[k];
        g_c[idx]    = c0[k];
    }
}

// ---------------- conv1: (1,24,24) -> conv3x3 SAME + relu + pool2 -> (10,12,12) ----------------
// block: 2 images, 288 threads = 2 * 144 pooled positions; each thread does all 10 channels
__global__ __launch_bounds__(288) void k_conv1(const float* __restrict__ imgs,
                                               const float* __restrict__ w1,
                                               const float* __restrict__ b1) {
    __shared__ float s_img[2][26 * 26];
    __shared__ float s_w[90];
    __shared__ float s_b[10];
    int tid = threadIdx.x;
    int i0  = blockIdx.x * 2;
    for (int idx = tid; idx < 2 * 676; idx += 288) ((float*)s_img)[idx] = 0.f;
    if (tid < 90) s_w[tid] = w1[tid];
    if (tid < 10) s_b[tid] = b1[tid];
    __syncthreads();
    for (int idx = tid; idx < 2 * 576; idx += 288) {
        int li = idx / 576, r = idx % 576;
        int y = r / 24, x = r % 24;
        s_img[li][(y + 1) * 26 + (x + 1)] = imgs[(size_t)(i0 + li) * 576 + r];
    }
    __syncthreads();
    int li  = tid / 144;
    int pos = tid % 144;
    int py = pos / 12, px = pos % 12;
    float p[4][4];
#pragma unroll
    for (int a = 0; a < 4; a++)
#pragma unroll
        for (int b = 0; b < 4; b++)
            p[a][b] = s_img[li][(2 * py + a) * 26 + (2 * px + b)];
    float* out = g_f1 + (size_t)(i0 + li) * 1440 + pos;
#pragma unroll
    for (int c = 0; c < 10; c++) {
        float bb = s_b[c];
        float a00 = bb, a01 = bb, a10 = bb, a11 = bb;
#pragma unroll
        for (int ky = 0; ky < 3; ky++)
#pragma unroll
            for (int kx = 0; kx < 3; kx++) {
                float w = s_w[c * 9 + ky * 3 + kx];
                a00 += p[ky][kx] * w;
                a01 += p[ky][kx + 1] * w;
                a10 += p[ky + 1][kx] * w;
                a11 += p[ky + 1][kx + 1] * w;
            }
        out[c * 144] = fmaxf(fmaxf(fmaxf(a00, a01), fmaxf(a10, a11)), 0.f);
    }
}

// ---------------- conv2: (10,12,12) -> (20,6,6) ----------------
// block: 4 images, 288 threads = 4 img * 2 chan-groups(10) * 36 pooled positions
__global__ __launch_bounds__(288) void k_conv2(const float* __restrict__ w2,
                                               const float* __restrict__ b2) {
    __shared__ float s_in[4][10][14 * 14];
    __shared__ float s_w[1800];
    __shared__ float s_b[20];
    int tid = threadIdx.x;
    int i0  = blockIdx.x * 4;
    for (int idx = tid; idx < 4 * 10 * 196; idx += 288) ((float*)s_in)[idx] = 0.f;
    for (int idx = tid; idx < 1800; idx += 288) s_w[idx] = w2[idx];
    if (tid < 20) s_b[tid] = b2[tid];
    __syncthreads();
    for (int idx = tid; idx < 4 * 1440; idx += 288) {
        int li = idx / 1440, r = idx % 1440;
        int c = r / 144, rr = r % 144;
        int y = rr / 12, x = rr % 12;
        s_in[li][c][(y + 1) * 14 + (x + 1)] = g_f1[(size_t)(i0 + li) * 1440 + r];
    }
    __syncthreads();
    int li  = tid / 72;
    int rem = tid % 72;
    int grp = rem / 36;
    int pos = rem % 36;
    int py = pos / 6, px = pos % 6;
    float acc[4][10];
#pragma unroll
    for (int c = 0; c < 10; c++) {
        float bb = s_b[grp * 10 + c];
        acc[0][c] = bb; acc[1][c] = bb; acc[2][c] = bb; acc[3][c] = bb;
    }
    for (int ic = 0; ic < 10; ic++) {
        float p[4][4];
#pragma unroll
        for (int a = 0; a < 4; a++)
#pragma unroll
            for (int b = 0; b < 4; b++)
                p[a][b] = s_in[li][ic][(2 * py + a) * 14 + (2 * px + b)];
#pragma unroll
        for (int c = 0; c < 10; c++) {
            const float* w = &s_w[((grp * 10 + c) * 10 + ic) * 9];
#pragma unroll
            for (int ky = 0; ky < 3; ky++)
#pragma unroll
                for (int kx = 0; kx < 3; kx++) {
                    float wv = w[ky * 3 + kx];
                    acc[0][c] += p[ky][kx] * wv;
                    acc[1][c] += p[ky][kx + 1] * wv;
                    acc[2][c] += p[ky + 1][kx] * wv;
                    acc[3][c] += p[ky + 1][kx + 1] * wv;
                }
        }
    }
    float* out = g_f2 + (size_t)(i0 + li) * 720 + pos;
#pragma unroll
    for (int c = 0; c < 10; c++) {
        float v = fmaxf(fmaxf(fmaxf(acc[0][c], acc[1][c]), fmaxf(acc[2][c], acc[3][c])), 0.f);
        out[(grp * 10 + c) * 36] = v;
    }
}

// ---------------- conv3: (20,6,6) -> (40,3,3), written directly in LSTM-input layout ----------------
// block: 4 images, 144 threads = 4 img * 4 chan-groups(10) * 9 pooled positions
__global__ __launch_bounds__(144) void k_conv3(const float* __restrict__ w3,
                                               const float* __restrict__ b3) {
    __shared__ float s_in[4][20][36];
    __shared__ float s_w[7200];
    __shared__ float s_b[40];
    int tid = threadIdx.x;  // 144
    int i0  = blockIdx.x * 4;
    for (int idx = tid; idx < 2880; idx += 144) {
        int li = idx / 720, r = idx % 720;
        ((float*)s_in)[li * 720 + r] = g_f2[(size_t)(i0 + li) * 720 + r];
    }
    for (int idx = tid; idx < 7200; idx += 144) s_w[idx] = w3[idx];
    if (tid < 40) s_b[tid] = b3[tid];
    __syncthreads();
    int li  = tid / 36;
    int rem = tid % 36;
    int grp = rem / 9;
    int pos = rem % 9;
    int py = pos / 3, px = pos % 3;
    float acc[4][10];
#pragma unroll
    for (int c = 0; c < 10; c++) {
        float bb = s_b[grp * 10 + c];
        acc[0][c] = bb; acc[1][c] = bb; acc[2][c] = bb; acc[3][c] = bb;
    }
    for (int ic = 0; ic < 20; ic++) {
        float p[4][4];
#pragma unroll
        for (int a = 0; a < 4; a++)
#pragma unroll
            for (int b = 0; b < 4; b++) {
                int rr = 2 * py + a - 1, cc = 2 * px + b - 1;
                p[a][b] = (rr >= 0 && rr < 6 && cc >= 0 && cc < 6)
                              ? s_in[li][ic][rr * 6 + cc] : 0.f;
            }
#pragma unroll
        for (int c = 0; c < 10; c++) {
            const float* w = &s_w[((grp * 10 + c) * 20 + ic) * 9];
#pragma unroll
            for (int ky = 0; ky < 3; ky++)
#pragma unroll
                for (int kx = 0; kx < 3; kx++) {
                    float wv = w[ky * 3 + kx];
                    acc[0][c] += p[ky][kx] * wv;
                    acc[1][c] += p[ky][kx + 1] * wv;
                    acc[2][c] += p[ky + 1][kx] * wv;
                    acc[3][c] += p[ky + 1][kx + 1] * wv;
                }
        }
    }
    int i = i0 + li;
    int t = i >> 9;      // /512
    int b = i & 511;
#pragma unroll
    for (int c0 = 0; c0 < 10; c0++) {
        int c = grp * 10 + c0;
        int e = c * 9 + pos;        // flatten (40,3,3)
        int r = e / 36, j = e % 36; // view(-1,36)
        float v = fmaxf(fmaxf(fmaxf(acc[0][c0], acc[1][c0]), fmaxf(acc[2][c0], acc[3][c0])), 0.f);
        g_x[((size_t)t * NB + b * 10 + r) * 36 + j] = v;
    }
}

// ---------------- xW precompute: G = x @ w_ih^T + (b_ih + b_hh), for ALL timesteps ----------------
// block tile 128x64, K=36, 256 threads, thread computes 8x4 (float4 stores)
__global__ __launch_bounds__(256) void k_xw(const float* __restrict__ w_ih,
                                            const float* __restrict__ b_ih,
                                            const float* __restrict__ b_hh) {
    __shared__ float A_s[36 * 132];  // x tile, K-major, padded stride
    __shared__ float B_s[36 * 68];   // w_ih tile, K-major
    int tid = threadIdx.x;
    long m0 = (long)blockIdx.x * 128;
    int  n0 = blockIdx.y * 64;
    for (int idx = tid; idx < 128 * 36; idx += 256) {
        int mm = idx / 36, k = idx % 36;
        A_s[k * 132 + mm] = g_x[m0 * 36 + idx];
    }
    for (int idx = tid; idx < 64 * 36; idx += 256) {
        int nn = idx / 36, k = idx % 36;
        B_s[k * 68 + nn] = w_ih[(n0 + nn) * 36 + k];
    }
    __syncthreads();
    int cg = tid & 15, rg = tid >> 4;
    float acc[8][4];
#pragma unroll
    for (int i = 0; i < 8; i++)
#pragma unroll
        for (int j = 0; j < 4; j++) acc[i][j] = 0.f;
#pragma unroll
    for (int k = 0; k < 36; k++) {
        float4 a0 = *(const float4*)&A_s[k * 132 + rg * 8];
        float4 a1 = *(const float4*)&A_s[k * 132 + rg * 8 + 4];
        float4 bv = *(const float4*)&B_s[k * 68 + cg * 4];
        float a[8] = {a0.x, a0.y, a0.z, a0.w, a1.x, a1.y, a1.z, a1.w};
        float b[4] = {bv.x, bv.y, bv.z, bv.w};
#pragma unroll
        for (int i = 0; i < 8; i++)
#pragma unroll
            for (int j = 0; j < 4; j++) acc[i][j] += a[i] * b[j];
    }
    float bias[4];
#pragma unroll
    for (int j = 0; j < 4; j++) {
        int col = n0 + cg * 4 + j;
        bias[j] = b_ih[col] + b_hh[col];
    }
#pragma unroll
    for (int i = 0; i < 8; i++) {
        long row = m0 + rg * 8 + i;
        float4 o = make_float4(acc[i][0] + bias[0], acc[i][1] + bias[1],
                               acc[i][2] + bias[2], acc[i][3] + bias[3]);
        *(float4*)&g_G[row * 448 + n0 + cg * 4] = o;
    }
}

// ---------------- fused LSTM step: gates = G[t] + h @ w_hh^T; activations; update h,c ----------------
// block: 128 rows x 16 hid-cols (x4 gates = 64 out cols). grid (40,7). 256 thr, thread = 8 rows x 1 col x 4 gates
__global__ __launch_bounds__(256) void k_step(const float* __restrict__ w_hh, int t) {
    extern __shared__ float sm[];
    float* A_s = sm;              // [112][132]  h tile, K-major padded
    float* B_s = sm + 112 * 132;  // [112][65]   w_hh tile, K-major padded
    const float* h_in  = g_h[t & 1];
    float*       h_out = g_h[(t & 1) ^ 1];
    int tid = threadIdx.x;
    int m0  = blockIdx.x * 128;
    int k0  = blockIdx.y * 16;
    for (int idx = tid; idx < 128 * 112; idx += 256) {
        int mm = idx / 112, k = idx % 112;
        A_s[k * 132 + mm] = h_in[(size_t)m0 * 112 + idx];
    }
    for (int idx = tid; idx < 64 * 112; idx += 256) {
        int nn = idx / 112, k = idx % 112;
        int wrow = (nn >> 4) * 112 + k0 + (nn & 15);
        B_s[k * 65 + nn] = w_hh[wrow * 112 + k];
    }
    __syncthreads();
    int kk = tid & 15, rg = tid >> 4;
    float acc[8][4];
#pragma unroll
    for (int i = 0; i < 8; i++)
#pragma unroll
        for (int g = 0; g < 4; g++) acc[i][g] = 0.f;
#pragma unroll 4
    for (int k = 0; k < 112; k++) {
        float4 a0 = *(const float4*)&A_s[k * 132 + rg * 8];
        float4 a1 = *(const float4*)&A_s[k * 132 + rg * 8 + 4];
        float a[8] = {a0.x, a0.y, a0.z, a0.w, a1.x, a1.y, a1.z, a1.w};
        float b[4];
#pragma unroll
        for (int g = 0; g < 4; g++) b[g] = B_s[k * 65 + g * 16 + kk];
#pragma unroll
        for (int i = 0; i < 8; i++)
#pragma unroll
            for (int g = 0; g < 4; g++) acc[i][g] += a[i] * b[g];
    }
    const float* Gt = g_G + (size_t)t * NB * G4;
    int kg = k0 + kk;
#pragma unroll
    for (int i = 0; i < 8; i++) {
        int m = m0 + rg * 8 + i;
        size_t gb = (size_t)m * 448 + kg;
        float gi = acc[i][0] + Gt[gb];
        float gf = acc[i][1] + Gt[gb + 112];
        float gg = acc[i][2] + Gt[gb + 224];
        float go = acc[i][3] + Gt[gb + 336];
        float is = 1.f / (1.f + expf(-gi));
        float fs = 1.f / (1.f + expf(-gf));
        float os = 1.f / (1.f + expf(-go));
        float gt = tanhf(gg);
        size_t hb = (size_t)m * 112 + kg;
        float cn = fs * g_c[hb] + is * gt;
        g_c[hb]   = cn;
        h_out[hb] = os * tanhf(cn);
    }
}

// ---------------- head: softmax(h @ wf^T + bf) ----------------
__global__ __launch_bounds__(256) void k_final(const float* __restrict__ wf,
                                               const float* __restrict__ bf,
                                               float* __restrict__ out) {
    int warp = threadIdx.x >> 5, lane = threadIdx.x & 31;
    int m = blockIdx.x * 8 + warp;
    const float* h = g_h[0];
    float p0 = 0.f, p1 = 0.f, p2 = 0.f;
    for (int k = lane; k < HID; k += 32) {
        float hv = h[(size_t)m * HID + k];
        p0 += hv * wf[k];
        p1 += hv * wf[HID + k];
        p2 += hv * wf[2 * HID + k];
    }
#pragma unroll
    for (int off = 16; off; off >>= 1) {
        p0 += __shfl_down_sync(0xffffffffu, p0, off);
        p1 += __shfl_down_sync(0xffffffffu, p1, off);
        p2 += __shfl_down_sync(0xffffffffu, p2, off);
    }
    if (lane == 0) {
        float l0 = p0 + bf[0], l1 = p1 + bf[1], l2 = p2 + bf[2];
        float mx = fmaxf(l0, fmaxf(l1, l2));
        float e0 = expf(l0 - mx), e1 = expf(l1 - mx), e2 = expf(l2 - mx);
        float s = e0 + e1 + e2;
        out[m * 3 + 0] = e0 / s;
        out[m * 3 + 1] = e1 / s;
        out[m * 3 + 2] = e2 / s;
    }
}

// ---------------- launch ----------------
extern "C" void kernel_launch(void* const* d_in, const int* in_sizes, int n_in,
                              void* d_out, int out_size) {
    const float* imgs = (const float*)d_in[0];
    const float* w1   = (const float*)d_in[1];
    const float* b1   = (const float*)d_in[2];
    const float* w2   = (const float*)d_in[3];
    const float* b2   = (const float*)d_in[4];
    const float* w3   = (const float*)d_in[5];
    const float* b3   = (const float*)d_in[6];
    const float* w_ih = (const float*)d_in[7];
    const float* w_hh = (const float*)d_in[8];
    const float* b_ih = (const float*)d_in[9];
    const float* b_hh = (const float*)d_in[10];
    const float* wf   = (const float*)d_in[11];
    const float* bf   = (const float*)d_in[12];
    const float* h0   = (const float*)d_in[13];
    const float* c0   = (const float*)d_in[14];

    size_t step_smem = (size_t)(112 * 132 + 112 * 65) * sizeof(float);  // 88,256 B
    cudaFuncSetAttribute(k_step, cudaFuncAttributeMaxDynamicSharedMemorySize, (int)(96 * 1024));

    k_init<<<(NB * HID + 255) / 256, 256>>>(h0, c0);
    k_conv1<<<TB / 2, 288>>>(imgs, w1, b1);
    k_conv2<<<TB / 4, 288>>>(w2, b2);
    k_conv3<<<TB / 4, 144>>>(w3, b3);
    dim3 gx(2560, 7);
    k_xw<<<gx, 256>>>(w_ih, b_ih, b_hh);
    dim3 gs(40, 7);
    for (int t = 0; t < T_STEPS; t++)
        k_step<<<gs, 256, step_smem>>>(w_hh, t);
    k_final<<<NB / 8, 256>>>(wf, bf, (float*)d_out);
}